// round 13
// baseline (speedup 1.0000x reference)
#include <cuda_runtime.h>
#include <cuda_bf16.h>
#include <cuda_fp16.h>
#include <cstdint>

// ---------------------------------------------------------------------------
// Problem constants
// ---------------------------------------------------------------------------
#define Bb 4
#define Cc 256
#define VC 128
#define NT 4096          // H*W
#define BM 64            // queries per CTA  (2 CTAs/SM)
#define BN 32            // keys per tile
#define NTILES (NT / BN) // 128
#define LOG2E 1.4426950408889634f

// Scratch
__device__ __nv_bfloat16 g_xhi[Bb * NT * Cc];   // x split, [b][n][c]
__device__ __nv_bfloat16 g_xlo[Bb * NT * Cc];
__device__ __nv_bfloat16 g_Whi[3 * VC * Cc];    // W split, [wi][d][c]
__device__ __nv_bfloat16 g_Wlo[3 * VC * Cc];
__device__ __nv_bfloat16 g_Qhi[Bb * NT * VC];   // Q*log2e split, [b][n][d]
__device__ __nv_bfloat16 g_Qlo[Bb * NT * VC];
__device__ __nv_bfloat16 g_Khi[Bb * NT * VC];
__device__ __nv_bfloat16 g_Klo[Bb * NT * VC];
__device__ __half        g_V  [Bb * VC * NT];   // V fp16, [b][d][n]

// ---------------------------------------------------------------------------
// helpers
// ---------------------------------------------------------------------------
__device__ __forceinline__ uint32_t smem_u32(const void* p) {
    uint32_t a;
    asm("{ .reg .u64 t; cvta.to.shared.u64 t, %1; cvt.u32.u64 %0, t; }"
        : "=r"(a) : "l"(p));
    return a;
}
__device__ __forceinline__ float ex2(float x) {
    float y;
    asm("ex2.approx.ftz.f32 %0, %1;" : "=f"(y) : "f"(x));
    return y;
}

#define CP_ASYNC16(dst, src) \
    asm volatile("cp.async.cg.shared.global [%0], [%1], 16;" \
                 :: "r"(dst), "l"(src) : "memory")
#define CP_COMMIT() asm volatile("cp.async.commit_group;" ::: "memory")
#define CP_WAIT1()  asm volatile("cp.async.wait_group 1;" ::: "memory")
#define CP_WAIT0()  asm volatile("cp.async.wait_group 0;" ::: "memory")

__device__ __forceinline__ void ldsm_x4(uint32_t addr, uint32_t& r0, uint32_t& r1,
                                        uint32_t& r2, uint32_t& r3) {
    asm volatile("ldmatrix.sync.aligned.m8n8.x4.shared.b16 {%0,%1,%2,%3}, [%4];"
                 : "=r"(r0), "=r"(r1), "=r"(r2), "=r"(r3) : "r"(addr));
}

__device__ __forceinline__ void mma_bf16(float* c, const uint32_t a[4],
                                         uint32_t b0, uint32_t b1) {
    asm volatile(
        "mma.sync.aligned.m16n8k16.row.col.f32.bf16.bf16.f32 "
        "{%0,%1,%2,%3}, {%4,%5,%6,%7}, {%8,%9}, {%0,%1,%2,%3};"
        : "+f"(c[0]), "+f"(c[1]), "+f"(c[2]), "+f"(c[3])
        : "r"(a[0]), "r"(a[1]), "r"(a[2]), "r"(a[3]), "r"(b0), "r"(b1));
}
__device__ __forceinline__ void mma_f16(float* c, const uint32_t a[4],
                                        uint32_t b0, uint32_t b1) {
    asm volatile(
        "mma.sync.aligned.m16n8k16.row.col.f32.f16.f16.f32 "
        "{%0,%1,%2,%3}, {%4,%5,%6,%7}, {%8,%9}, {%0,%1,%2,%3};"
        : "+f"(c[0]), "+f"(c[1]), "+f"(c[2]), "+f"(c[3])
        : "r"(a[0]), "r"(a[1]), "r"(a[2]), "r"(a[3]), "r"(b0), "r"(b1));
}

__device__ __forceinline__ void split_bf(float v, __nv_bfloat16& h, __nv_bfloat16& l) {
    h = __float2bfloat16_rn(v);
    l = __float2bfloat16_rn(v - __bfloat162float(h));
}
__device__ __forceinline__ uint32_t pk(__nv_bfloat16 a, __nv_bfloat16 b) {
    __nv_bfloat162 t = __halves2bfloat162(a, b);
    uint32_t u;
    *reinterpret_cast<__nv_bfloat162*>(&u) = t;
    return u;
}
__device__ __forceinline__ uint32_t pkh(__half a, __half b) {
    __half2 t = __halves2half2(a, b);
    uint32_t u;
    *reinterpret_cast<__half2*>(&u) = t;
    return u;
}

// swizzled byte offsets: 256B rows (16 chunks of 16B), 128B rows (8 chunks)
__device__ __forceinline__ uint32_t swz_q(int row, int ch) {
    return (uint32_t)(row * 256 + ((ch ^ (row & 7)) << 4));
}
__device__ __forceinline__ uint32_t swz_v(int row, int ch) {
    return (uint32_t)(row * 128 + ((ch ^ (row & 7)) << 4));
}

// ---------------------------------------------------------------------------
// W split: Wq/Wk/Wv [d][c] fp32 -> g_Whi/g_Wlo bf16 [wi][d][c]
// ---------------------------------------------------------------------------
__global__ __launch_bounds__(256) void wsplit_kernel(
    const float* __restrict__ Wq,
    const float* __restrict__ Wk,
    const float* __restrict__ Wv)
{
    const int idx = blockIdx.x * 256 + threadIdx.x;
    const int f0  = idx * 4;
    const int wi  = f0 / (VC * Cc);
    const int off = f0 - wi * (VC * Cc);
    const float* W = (wi == 0) ? Wq : (wi == 1) ? Wk : Wv;
    float4 v = *(const float4*)(W + off);
    __nv_bfloat16 h0, l0, h1, l1, h2, l2, h3, l3;
    split_bf(v.x, h0, l0); split_bf(v.y, h1, l1);
    split_bf(v.z, h2, l2); split_bf(v.w, h3, l3);
    size_t o = (size_t)wi * VC * Cc + off;
    *(uint2*)(g_Whi + o) = make_uint2(pk(h0, h1), pk(h2, h3));
    *(uint2*)(g_Wlo + o) = make_uint2(pk(l0, l1), pk(l2, l3));
}

// ---------------------------------------------------------------------------
// x split/transpose: x [b][c][n] fp32 -> g_xhi/g_xlo [b][n][c] bf16.
// ---------------------------------------------------------------------------
__global__ __launch_bounds__(256) void xsplit_kernel(const float* __restrict__ x)
{
    __shared__ float T[64][65];
    const int b  = blockIdx.z;
    const int c0 = blockIdx.y * 64;
    const int n0 = blockIdx.x * 64;
    const int tid = threadIdx.x;

    #pragma unroll
    for (int i = tid; i < 64 * 16; i += 256) {
        int c = i >> 4, n4 = i & 15;
        float4 v = *(const float4*)(x + ((size_t)b * Cc + c0 + c) * NT + n0 + n4 * 4);
        T[c][n4 * 4 + 0] = v.x; T[c][n4 * 4 + 1] = v.y;
        T[c][n4 * 4 + 2] = v.z; T[c][n4 * 4 + 3] = v.w;
    }
    __syncthreads();
    #pragma unroll
    for (int i = tid; i < 64 * 32; i += 256) {
        int n = i >> 5, c2 = i & 31;
        float f0 = T[c2 * 2][n], f1 = T[c2 * 2 + 1][n];
        __nv_bfloat16 h0, l0, h1, l1;
        split_bf(f0, h0, l0);
        split_bf(f1, h1, l1);
        size_t off = ((size_t)b * NT + n0 + n) * Cc + c0 + c2 * 2;
        *(uint32_t*)(g_xhi + off) = pk(h0, h1);
        *(uint32_t*)(g_xlo + off) = pk(l0, l1);
    }
}

// ---------------------------------------------------------------------------
// Fused QKV projection (split-bf16, 3-pass). A staged once, B double-buffered.
// grid (NT/128, Bb), 256 threads, smem 192KB. (unchanged from R10)
// ---------------------------------------------------------------------------
#define FA_OFF(kc, comp) (((kc) * 2 + (comp)) * 16384)
#define FB_OFF 131072
#define FB_BUF 32768
#define PF_SMEM 196608

extern __shared__ char proj_sm[];

__device__ __forceinline__ void proj_load_B(uint32_t sb, int wi, int kc, int buf, int tid)
{
    #pragma unroll
    for (int i = tid; i < 2048; i += 256) {
        int comp = i >> 10, row = (i >> 3) & 127, ch = i & 7;
        const __nv_bfloat16* src = comp ? g_Wlo : g_Whi;
        const char* g = (const char*)(src + (size_t)wi * VC * Cc + (size_t)row * Cc + kc * 64)
                        + ch * 16;
        CP_ASYNC16(sb + FB_OFF + buf * FB_BUF + comp * 16384 + swz_v(row, ch), g);
    }
}

__global__ __launch_bounds__(256, 1) void proj_fused_kernel()
{
    const int b  = blockIdx.y;
    const int n0 = blockIdx.x * 128;

    const int tid  = threadIdx.x;
    const int w    = tid >> 5;
    const int lane = tid & 31;
    const int q0   = w * 16;

    char* psm = proj_sm;
    const uint32_t sb = smem_u32(psm);

    const int a_row = q0 + (lane & 15);
    const int a_c16 = lane >> 4;
    const int b_row = (lane & 7) + ((lane >> 4) << 3);
    const int b_ch  = (lane >> 3) & 1;

    #pragma unroll
    for (int i = tid; i < 8192; i += 256) {
        int comp = i >> 12;
        int rem  = i & 4095;
        int kc   = rem >> 10;
        int row  = (rem >> 3) & 127;
        int ch   = rem & 7;
        const __nv_bfloat16* src = comp ? g_xlo : g_xhi;
        const char* g = (const char*)(src + ((size_t)b * NT + n0 + row) * Cc + kc * 64)
                        + ch * 16;
        CP_ASYNC16(sb + FA_OFF(kc, comp) + swz_v(row, ch), g);
    }
    proj_load_B(sb, 0, 0, 0, tid);
    CP_COMMIT();

    float C[16][4];
    const int r  = lane >> 2;
    const int cq = (lane & 3) * 2;

    #pragma unroll 1
    for (int it = 0; it < 12; it++) {
        const int wi  = it >> 2;
        const int kc  = it & 3;
        const int buf = it & 1;

        if (kc == 0) {
            #pragma unroll
            for (int i = 0; i < 16; i++)
                #pragma unroll
                for (int j = 0; j < 4; j++) C[i][j] = 0.f;
        }

        __syncthreads();
        if (it + 1 < 12) {
            proj_load_B(sb, (it + 1) >> 2, (it + 1) & 3, buf ^ 1, tid);
            CP_COMMIT();
            CP_WAIT1();
        } else {
            CP_WAIT0();
        }
        __syncthreads();

        const uint32_t bh_base = sb + FB_OFF + buf * FB_BUF;
        const uint32_t bl_base = bh_base + 16384;
        const uint32_t ah_base = sb + FA_OFF(kc, 0);
        const uint32_t al_base = sb + FA_OFF(kc, 1);

        #pragma unroll
        for (int kk = 0; kk < 4; kk++) {
            uint32_t ah[4], al[4];
            ldsm_x4(ah_base + swz_v(a_row, 2 * kk + a_c16), ah[0], ah[1], ah[2], ah[3]);
            ldsm_x4(al_base + swz_v(a_row, 2 * kk + a_c16), al[0], al[1], al[2], al[3]);
            #pragma unroll
            for (int nt = 0; nt < 8; nt++) {
                uint32_t bh0, bh1, bh2, bh3, bl0, bl1, bl2, bl3;
                ldsm_x4(bh_base + swz_v(nt * 16 + b_row, 2 * kk + b_ch), bh0, bh1, bh2, bh3);
                ldsm_x4(bl_base + swz_v(nt * 16 + b_row, 2 * kk + b_ch), bl0, bl1, bl2, bl3);
                mma_bf16(C[2 * nt],     ah, bh0, bh1);
                mma_bf16(C[2 * nt + 1], ah, bh2, bh3);
                mma_bf16(C[2 * nt],     ah, bl0, bl1);
                mma_bf16(C[2 * nt + 1], ah, bl2, bl3);
                mma_bf16(C[2 * nt],     al, bh0, bh1);
                mma_bf16(C[2 * nt + 1], al, bh2, bh3);
            }
        }

        if (kc == 3) {
            if (wi < 2) {
                __nv_bfloat16* Bh = (wi == 0) ? g_Qhi : g_Khi;
                __nv_bfloat16* Bl = (wi == 0) ? g_Qlo : g_Klo;
                const float sc = (wi == 0) ? LOG2E : 1.0f;
                #pragma unroll
                for (int nt = 0; nt < 16; nt++) {
                    int d = nt * 8 + cq;
                    __nv_bfloat16 h0, l0, h1, l1;
                    split_bf(C[nt][0] * sc, h0, l0);
                    split_bf(C[nt][1] * sc, h1, l1);
                    size_t o0 = ((size_t)b * NT + n0 + q0 + r) * VC + d;
                    *(uint32_t*)(Bh + o0) = pk(h0, h1);
                    *(uint32_t*)(Bl + o0) = pk(l0, l1);
                    split_bf(C[nt][2] * sc, h0, l0);
                    split_bf(C[nt][3] * sc, h1, l1);
                    size_t o1 = o0 + (size_t)8 * VC;
                    *(uint32_t*)(Bh + o1) = pk(h0, h1);
                    *(uint32_t*)(Bl + o1) = pk(l0, l1);
                }
            } else {
                float* Vt = (float*)psm;   // 64 x 132 floats
                #pragma unroll
                for (int h = 0; h < 2; h++) {
                    __syncthreads();
                    #pragma unroll
                    for (int nt = h * 8; nt < h * 8 + 8; nt++) {
                        int dl = nt * 8 + cq - h * 64;
                        Vt[dl * 132 + q0 + r]           = C[nt][0];
                        Vt[(dl + 1) * 132 + q0 + r]     = C[nt][1];
                        Vt[dl * 132 + q0 + r + 8]       = C[nt][2];
                        Vt[(dl + 1) * 132 + q0 + r + 8] = C[nt][3];
                    }
                    __syncthreads();
                    #pragma unroll
                    for (int i = tid; i < 64 * 64; i += 256) {
                        int dd = i >> 6, n2 = i & 63;
                        __half2 hv = __floats2half2_rn(Vt[dd * 132 + n2 * 2],
                                                       Vt[dd * 132 + n2 * 2 + 1]);
                        *(__half2*)(g_V + ((size_t)b * VC + h * 64 + dd) * NT + n0 + n2 * 2) = hv;
                    }
                }
            }
        }
    }
}

// ---------------------------------------------------------------------------
// Flash attention, 2 CTAs/SM: BM=64 (4 warps), BN=32, single barrier/tile.
// smem (96KB/CTA): Qhi 0 (16K), Qlo 16K, Khi[2] 32K (8K bufs),
// Klo[2] 48K, V[2] 64K (16K bufs, 128B padded rows).
// Pipeline: wait0 -> barrier -> prefetch(t+1) -> compute(t). Race-free:
// all reads of buf^1 (tile t-1) happen before the barrier.
// ---------------------------------------------------------------------------
#define QHI_OFF 0
#define QLO_OFF 16384
#define KHI_OFF 32768
#define KLO_OFF 49152
#define V_OFF   65536
#define KBUF2   8192
#define VBUF2   16384
#define S_TOTAL 98304

extern __shared__ char fa_sm[];

__device__ __forceinline__ void load_kv(uint32_t sbase, int b, int t, int buf, int tid)
{
    const int k0 = t * BN;
    // K: 32 rows x 16 chunks x 2 comps
    #pragma unroll
    for (int i = tid; i < 1024; i += 128) {
        int comp = i >> 9, row = (i >> 4) & 31, ch = i & 15;
        const __nv_bfloat16* src = comp ? g_Klo : g_Khi;
        const char* g = (const char*)(src + ((size_t)b * NT + k0 + row) * VC) + ch * 16;
        uint32_t dst = sbase + (comp ? KLO_OFF : KHI_OFF) + buf * KBUF2;
        CP_ASYNC16(dst + swz_q(row, ch), g);
    }
    // V: 128 d-rows x 4 chunks (32 keys), rows padded to 128B
    #pragma unroll
    for (int i = tid; i < 512; i += 128) {
        int row = i >> 2, ch = i & 3;
        const char* g = (const char*)(g_V + ((size_t)b * VC + row) * NT + k0) + ch * 16;
        CP_ASYNC16(sbase + V_OFF + buf * VBUF2 + swz_v(row, ch), g);
    }
}

__global__ __launch_bounds__(128, 2) void fa_kernel(float* __restrict__ out)
{
    const int tid  = threadIdx.x;
    const int w    = tid >> 5;
    const int lane = tid & 31;
    const int b    = blockIdx.y;
    const int n0   = blockIdx.x * BM;
    const int q0   = w * 16;

    char* sm = fa_sm;
    const uint32_t sbase = smem_u32(sm);

    // stage Q (hi/lo): 64 rows x 16 chunks x 2 comps
    #pragma unroll
    for (int i = tid; i < 2048; i += 128) {
        int comp = i >> 10, row = (i >> 4) & 63, ch = i & 15;
        const __nv_bfloat16* src = comp ? g_Qlo : g_Qhi;
        const char* g = (const char*)(src + ((size_t)b * NT + n0 + row) * VC) + ch * 16;
        uint32_t dst = sbase + (comp ? QLO_OFF : QHI_OFF);
        CP_ASYNC16(dst + swz_q(row, ch), g);
    }
    load_kv(sbase, b, 0, 0, tid);
    CP_COMMIT();

    float O[16][4];
    #pragma unroll
    for (int i = 0; i < 16; i++)
        #pragma unroll
        for (int j = 0; j < 4; j++) O[i][j] = 0.f;
    float rs0 = 0.f, rs1 = 0.f;
    float M0 = -1e30f, M1 = -1e30f;

    const int a_row = q0 + (lane & 15);
    const int a_ch  = (lane >> 4);
    const int b_row = (lane & 7) + ((lane >> 4) << 3);
    const int b_ch  = ((lane >> 3) & 1);

    #pragma unroll 1
    for (int t = 0; t < NTILES; t++) {
        const int buf = t & 1;
        CP_WAIT0();        // tile t resident (only outstanding group)
        __syncthreads();   // visibility + everyone done with buf^1
        if (t + 1 < NTILES) {
            load_kv(sbase, b, t + 1, buf ^ 1, tid);
            CP_COMMIT();
        }

        const uint32_t kh_base = sbase + KHI_OFF + buf * KBUF2;
        const uint32_t kl_base = sbase + KLO_OFF + buf * KBUF2;
        const uint32_t v_base  = sbase + V_OFF   + buf * VBUF2;

        // ---- S = Q K^T (bf16 3-pass), base-2 logits (Q pre-scaled) ----
        float C[4][4];
        #pragma unroll
        for (int i = 0; i < 4; i++)
            #pragma unroll
            for (int j = 0; j < 4; j++) C[i][j] = 0.f;

        #pragma unroll
        for (int kc = 0; kc < 8; kc++) {
            uint32_t aqh[4], aql[4];
            ldsm_x4(sbase + QHI_OFF + swz_q(a_row, 2 * kc + a_ch),
                    aqh[0], aqh[1], aqh[2], aqh[3]);
            ldsm_x4(sbase + QLO_OFF + swz_q(a_row, 2 * kc + a_ch),
                    aql[0], aql[1], aql[2], aql[3]);
            #pragma unroll
            for (int ntp = 0; ntp < 2; ntp++) {
                uint32_t bh0, bh1, bh2, bh3, bl0, bl1, bl2, bl3;
                ldsm_x4(kh_base + swz_q(ntp * 16 + b_row, 2 * kc + b_ch),
                        bh0, bh1, bh2, bh3);
                ldsm_x4(kl_base + swz_q(ntp * 16 + b_row, 2 * kc + b_ch),
                        bl0, bl1, bl2, bl3);
                mma_bf16(C[2 * ntp],     aqh, bh0, bh1);
                mma_bf16(C[2 * ntp + 1], aqh, bh2, bh3);
                mma_bf16(C[2 * ntp],     aqh, bl0, bl1);
                mma_bf16(C[2 * ntp + 1], aqh, bl2, bl3);
                mma_bf16(C[2 * ntp],     aql, bh0, bh1);
                mma_bf16(C[2 * ntp + 1], aql, bh2, bh3);
            }
        }

        // ---- row max + rescale ----
        float tm0 = fmaxf(fmaxf(C[0][0], C[0][1]), fmaxf(C[1][0], C[1][1]));
        float tm1 = fmaxf(fmaxf(C[0][2], C[0][3]), fmaxf(C[1][2], C[1][3]));
        tm0 = fmaxf(tm0, fmaxf(fmaxf(C[2][0], C[2][1]), fmaxf(C[3][0], C[3][1])));
        tm1 = fmaxf(tm1, fmaxf(fmaxf(C[2][2], C[2][3]), fmaxf(C[3][2], C[3][3])));
        tm0 = fmaxf(tm0, __shfl_xor_sync(0xffffffffu, tm0, 1));
        tm0 = fmaxf(tm0, __shfl_xor_sync(0xffffffffu, tm0, 2));
        tm1 = fmaxf(tm1, __shfl_xor_sync(0xffffffffu, tm1, 1));
        tm1 = fmaxf(tm1, __shfl_xor_sync(0xffffffffu, tm1, 2));
        const float M0n = fmaxf(M0, tm0);
        const float M1n = fmaxf(M1, tm1);
        const float s0 = ex2(M0 - M0n);
        const float s1 = ex2(M1 - M1n);
        M0 = M0n; M1 = M1n;
        rs0 *= s0; rs1 *= s1;

        if (!__all_sync(0xffffffffu, (s0 == 1.0f) & (s1 == 1.0f))) {
            #pragma unroll
            for (int nt = 0; nt < 16; nt++) {
                O[nt][0] *= s0; O[nt][1] *= s0;
                O[nt][2] *= s1; O[nt][3] *= s1;
            }
        }

        // ---- interleaved: per kc group, softmax (exp2/pack) then PV mma ----
        #pragma unroll
        for (int kc = 0; kc < 2; kc++) {
            uint32_t aph[4];
            {
                const int nt = 2 * kc;
                float p0 = ex2(C[nt][0] - M0), p1 = ex2(C[nt][1] - M0);
                float p2 = ex2(C[nt][2] - M1), p3 = ex2(C[nt][3] - M1);
                rs0 += p0 + p1; rs1 += p2 + p3;
                aph[0] = pkh(__float2half_rn(p0), __float2half_rn(p1));
                aph[1] = pkh(__float2half_rn(p2), __float2half_rn(p3));
                p0 = ex2(C[nt + 1][0] - M0); p1 = ex2(C[nt + 1][1] - M0);
                p2 = ex2(C[nt + 1][2] - M1); p3 = ex2(C[nt + 1][3] - M1);
                rs0 += p0 + p1; rs1 += p2 + p3;
                aph[2] = pkh(__float2half_rn(p0), __float2half_rn(p1));
                aph[3] = pkh(__float2half_rn(p2), __float2half_rn(p3));
            }
            #pragma unroll
            for (int ntp = 0; ntp < 8; ntp++) {
                uint32_t v0, v1, v2, v3;
                ldsm_x4(v_base + swz_v(ntp * 16 + b_row, 2 * kc + b_ch),
                        v0, v1, v2, v3);
                mma_f16(O[2 * ntp],     aph, v0, v1);
                mma_f16(O[2 * ntp + 1], aph, v2, v3);
            }
        }
    }

    // ---- finalize ----
    rs0 += __shfl_xor_sync(0xffffffffu, rs0, 1);
    rs0 += __shfl_xor_sync(0xffffffffu, rs0, 2);
    rs1 += __shfl_xor_sync(0xffffffffu, rs1, 1);
    rs1 += __shfl_xor_sync(0xffffffffu, rs1, 2);
    const float inv0 = 1.0f / rs0;
    const float inv1 = 1.0f / rs1;

    __syncthreads();
    float* Ot = (float*)(sm + KHI_OFF);   // 128 x 68 floats (34816B) fits K/V region
    const int r  = lane >> 2;
    const int cc = (lane & 3) * 2;
    #pragma unroll
    for (int nt = 0; nt < 16; nt++) {
        int d = nt * 8 + cc;
        Ot[d * 68 + q0 + r]           = O[nt][0] * inv0;
        Ot[(d + 1) * 68 + q0 + r]     = O[nt][1] * inv0;
        Ot[d * 68 + q0 + r + 8]       = O[nt][2] * inv1;
        Ot[(d + 1) * 68 + q0 + r + 8] = O[nt][3] * inv1;
    }
    __syncthreads();

    float* outb = out + (size_t)b * VC * NT;
    #pragma unroll
    for (int i = tid; i < VC * BM; i += 128) {
        int d = i >> 6, q = i & 63;
        outb[(size_t)d * NT + n0 + q] = Ot[d * 68 + q];
    }
}

// ---------------------------------------------------------------------------
extern "C" void kernel_launch(void* const* d_in, const int* in_sizes, int n_in,
                              void* d_out, int out_size)
{
    const float* x  = (const float*)d_in[0];
    const float* Wq = (const float*)d_in[1];
    const float* Wk = (const float*)d_in[2];
    const float* Wv = (const float*)d_in[3];
    float* out = (float*)d_out;

    wsplit_kernel<<<3 * VC * Cc / 4 / 256, 256>>>(Wq, Wk, Wv);

    dim3 g0(NT / 64, Cc / 64, Bb);
    xsplit_kernel<<<g0, 256>>>(x);

    cudaFuncSetAttribute(proj_fused_kernel, cudaFuncAttributeMaxDynamicSharedMemorySize, PF_SMEM);
    dim3 g1(NT / 128, Bb);
    proj_fused_kernel<<<g1, 256, PF_SMEM>>>();

    cudaFuncSetAttribute(fa_kernel, cudaFuncAttributeMaxDynamicSharedMemorySize, S_TOTAL);
    dim3 g2(NT / BM, Bb);
    fa_kernel<<<g2, 128, S_TOTAL>>>(out);
}

// round 14
// speedup vs baseline: 1.2262x; 1.2262x over previous
#include <cuda_runtime.h>
#include <cuda_bf16.h>
#include <cuda_fp16.h>
#include <cstdint>

// ---------------------------------------------------------------------------
// Problem constants
// ---------------------------------------------------------------------------
#define Bb 4
#define Cc 256
#define VC 128
#define NT 4096          // H*W
#define BM 128           // queries per CTA
#define BN 64            // keys per tile
#define NTILES (NT / BN) // 64
#define LOG2E 1.4426950408889634f

// Scratch
__device__ __nv_bfloat16 g_xhi[Bb * NT * Cc];   // x split, [b][n][c]
__device__ __nv_bfloat16 g_xlo[Bb * NT * Cc];
__device__ __nv_bfloat16 g_Whi[3 * VC * Cc];    // W split, [wi][d][c]
__device__ __nv_bfloat16 g_Wlo[3 * VC * Cc];
__device__ __half        g_Qhi[Bb * NT * VC];   // Q*log2e fp16 split, [b][n][d]
__device__ __half        g_Qlo[Bb * NT * VC];
__device__ __half        g_K  [Bb * NT * VC];   // K single fp16, [b][n][d]
__device__ __half        g_V  [Bb * VC * NT];   // V fp16, [b][d][n]

// ---------------------------------------------------------------------------
// helpers
// ---------------------------------------------------------------------------
__device__ __forceinline__ uint32_t smem_u32(const void* p) {
    uint32_t a;
    asm("{ .reg .u64 t; cvta.to.shared.u64 t, %1; cvt.u32.u64 %0, t; }"
        : "=r"(a) : "l"(p));
    return a;
}
__device__ __forceinline__ float ex2(float x) {
    float y;
    asm("ex2.approx.ftz.f32 %0, %1;" : "=f"(y) : "f"(x));
    return y;
}

#define CP_ASYNC16(dst, src) \
    asm volatile("cp.async.cg.shared.global [%0], [%1], 16;" \
                 :: "r"(dst), "l"(src) : "memory")
#define CP_COMMIT() asm volatile("cp.async.commit_group;" ::: "memory")
#define CP_WAIT1()  asm volatile("cp.async.wait_group 1;" ::: "memory")
#define CP_WAIT0()  asm volatile("cp.async.wait_group 0;" ::: "memory")

__device__ __forceinline__ void ldsm_x4(uint32_t addr, uint32_t& r0, uint32_t& r1,
                                        uint32_t& r2, uint32_t& r3) {
    asm volatile("ldmatrix.sync.aligned.m8n8.x4.shared.b16 {%0,%1,%2,%3}, [%4];"
                 : "=r"(r0), "=r"(r1), "=r"(r2), "=r"(r3) : "r"(addr));
}

__device__ __forceinline__ void mma_bf16(float* c, const uint32_t a[4],
                                         uint32_t b0, uint32_t b1) {
    asm volatile(
        "mma.sync.aligned.m16n8k16.row.col.f32.bf16.bf16.f32 "
        "{%0,%1,%2,%3}, {%4,%5,%6,%7}, {%8,%9}, {%0,%1,%2,%3};"
        : "+f"(c[0]), "+f"(c[1]), "+f"(c[2]), "+f"(c[3])
        : "r"(a[0]), "r"(a[1]), "r"(a[2]), "r"(a[3]), "r"(b0), "r"(b1));
}
__device__ __forceinline__ void mma_f16(float* c, const uint32_t a[4],
                                        uint32_t b0, uint32_t b1) {
    asm volatile(
        "mma.sync.aligned.m16n8k16.row.col.f32.f16.f16.f32 "
        "{%0,%1,%2,%3}, {%4,%5,%6,%7}, {%8,%9}, {%0,%1,%2,%3};"
        : "+f"(c[0]), "+f"(c[1]), "+f"(c[2]), "+f"(c[3])
        : "r"(a[0]), "r"(a[1]), "r"(a[2]), "r"(a[3]), "r"(b0), "r"(b1));
}

__device__ __forceinline__ void split_bf(float v, __nv_bfloat16& h, __nv_bfloat16& l) {
    h = __float2bfloat16_rn(v);
    l = __float2bfloat16_rn(v - __bfloat162float(h));
}
__device__ __forceinline__ void split_h(float v, __half& h, __half& l) {
    h = __float2half_rn(v);
    l = __float2half_rn(v - __half2float(h));
}
__device__ __forceinline__ uint32_t pk(__nv_bfloat16 a, __nv_bfloat16 b) {
    __nv_bfloat162 t = __halves2bfloat162(a, b);
    uint32_t u;
    *reinterpret_cast<__nv_bfloat162*>(&u) = t;
    return u;
}
__device__ __forceinline__ uint32_t pkh(__half a, __half b) {
    __half2 t = __halves2half2(a, b);
    uint32_t u;
    *reinterpret_cast<__half2*>(&u) = t;
    return u;
}

// swizzled byte offsets: 256B rows (16 chunks of 16B), 128B rows (8 chunks)
__device__ __forceinline__ uint32_t swz_q(int row, int ch) {
    return (uint32_t)(row * 256 + ((ch ^ (row & 7)) << 4));
}
__device__ __forceinline__ uint32_t swz_v(int row, int ch) {
    return (uint32_t)(row * 128 + ((ch ^ (row & 7)) << 4));
}

// ---------------------------------------------------------------------------
// W split: Wq/Wk/Wv [d][c] fp32 -> g_Whi/g_Wlo bf16 [wi][d][c]
// ---------------------------------------------------------------------------
__global__ __launch_bounds__(256) void wsplit_kernel(
    const float* __restrict__ Wq,
    const float* __restrict__ Wk,
    const float* __restrict__ Wv)
{
    const int idx = blockIdx.x * 256 + threadIdx.x;
    const int f0  = idx * 4;
    const int wi  = f0 / (VC * Cc);
    const int off = f0 - wi * (VC * Cc);
    const float* W = (wi == 0) ? Wq : (wi == 1) ? Wk : Wv;
    float4 v = *(const float4*)(W + off);
    __nv_bfloat16 h0, l0, h1, l1, h2, l2, h3, l3;
    split_bf(v.x, h0, l0); split_bf(v.y, h1, l1);
    split_bf(v.z, h2, l2); split_bf(v.w, h3, l3);
    size_t o = (size_t)wi * VC * Cc + off;
    *(uint2*)(g_Whi + o) = make_uint2(pk(h0, h1), pk(h2, h3));
    *(uint2*)(g_Wlo + o) = make_uint2(pk(l0, l1), pk(l2, l3));
}

// ---------------------------------------------------------------------------
// x split/transpose: x [b][c][n] fp32 -> g_xhi/g_xlo [b][n][c] bf16.
// ---------------------------------------------------------------------------
__global__ __launch_bounds__(256) void xsplit_kernel(const float* __restrict__ x)
{
    __shared__ float T[64][65];
    const int b  = blockIdx.z;
    const int c0 = blockIdx.y * 64;
    const int n0 = blockIdx.x * 64;
    const int tid = threadIdx.x;

    #pragma unroll
    for (int i = tid; i < 64 * 16; i += 256) {
        int c = i >> 4, n4 = i & 15;
        float4 v = *(const float4*)(x + ((size_t)b * Cc + c0 + c) * NT + n0 + n4 * 4);
        T[c][n4 * 4 + 0] = v.x; T[c][n4 * 4 + 1] = v.y;
        T[c][n4 * 4 + 2] = v.z; T[c][n4 * 4 + 3] = v.w;
    }
    __syncthreads();
    #pragma unroll
    for (int i = tid; i < 64 * 32; i += 256) {
        int n = i >> 5, c2 = i & 31;
        float f0 = T[c2 * 2][n], f1 = T[c2 * 2 + 1][n];
        __nv_bfloat16 h0, l0, h1, l1;
        split_bf(f0, h0, l0);
        split_bf(f1, h1, l1);
        size_t off = ((size_t)b * NT + n0 + n) * Cc + c0 + c2 * 2;
        *(uint32_t*)(g_xhi + off) = pk(h0, h1);
        *(uint32_t*)(g_xlo + off) = pk(l0, l1);
    }
}

// ---------------------------------------------------------------------------
// Fused QKV projection (split-bf16, 3-pass). A staged once, B double-buffered.
// Epilogue: Q -> fp16 hi/lo (scaled log2e), K -> single fp16, V -> fp16 [b][d][n].
// grid (NT/128, Bb), 256 threads, smem 192KB.
// ---------------------------------------------------------------------------
#define FA_OFF(kc, comp) (((kc) * 2 + (comp)) * 16384)
#define FB_OFF 131072
#define FB_BUF 32768
#define PF_SMEM 196608

extern __shared__ char proj_sm[];

__device__ __forceinline__ void proj_load_B(uint32_t sb, int wi, int kc, int buf, int tid)
{
    #pragma unroll
    for (int i = tid; i < 2048; i += 256) {
        int comp = i >> 10, row = (i >> 3) & 127, ch = i & 7;
        const __nv_bfloat16* src = comp ? g_Wlo : g_Whi;
        const char* g = (const char*)(src + (size_t)wi * VC * Cc + (size_t)row * Cc + kc * 64)
                        + ch * 16;
        CP_ASYNC16(sb + FB_OFF + buf * FB_BUF + comp * 16384 + swz_v(row, ch), g);
    }
}

__global__ __launch_bounds__(256, 1) void proj_fused_kernel()
{
    const int b  = blockIdx.y;
    const int n0 = blockIdx.x * 128;

    const int tid  = threadIdx.x;
    const int w    = tid >> 5;
    const int lane = tid & 31;
    const int q0   = w * 16;

    char* psm = proj_sm;
    const uint32_t sb = smem_u32(psm);

    const int a_row = q0 + (lane & 15);
    const int a_c16 = lane >> 4;
    const int b_row = (lane & 7) + ((lane >> 4) << 3);
    const int b_ch  = (lane >> 3) & 1;

    #pragma unroll
    for (int i = tid; i < 8192; i += 256) {
        int comp = i >> 12;
        int rem  = i & 4095;
        int kc   = rem >> 10;
        int row  = (rem >> 3) & 127;
        int ch   = rem & 7;
        const __nv_bfloat16* src = comp ? g_xlo : g_xhi;
        const char* g = (const char*)(src + ((size_t)b * NT + n0 + row) * Cc + kc * 64)
                        + ch * 16;
        CP_ASYNC16(sb + FA_OFF(kc, comp) + swz_v(row, ch), g);
    }
    proj_load_B(sb, 0, 0, 0, tid);
    CP_COMMIT();

    float C[16][4];
    const int r  = lane >> 2;
    const int cq = (lane & 3) * 2;

    #pragma unroll 1
    for (int it = 0; it < 12; it++) {
        const int wi  = it >> 2;
        const int kc  = it & 3;
        const int buf = it & 1;

        if (kc == 0) {
            #pragma unroll
            for (int i = 0; i < 16; i++)
                #pragma unroll
                for (int j = 0; j < 4; j++) C[i][j] = 0.f;
        }

        __syncthreads();
        if (it + 1 < 12) {
            proj_load_B(sb, (it + 1) >> 2, (it + 1) & 3, buf ^ 1, tid);
            CP_COMMIT();
            CP_WAIT1();
        } else {
            CP_WAIT0();
        }
        __syncthreads();

        const uint32_t bh_base = sb + FB_OFF + buf * FB_BUF;
        const uint32_t bl_base = bh_base + 16384;
        const uint32_t ah_base = sb + FA_OFF(kc, 0);
        const uint32_t al_base = sb + FA_OFF(kc, 1);

        #pragma unroll
        for (int kk = 0; kk < 4; kk++) {
            uint32_t ah[4], al[4];
            ldsm_x4(ah_base + swz_v(a_row, 2 * kk + a_c16), ah[0], ah[1], ah[2], ah[3]);
            ldsm_x4(al_base + swz_v(a_row, 2 * kk + a_c16), al[0], al[1], al[2], al[3]);
            #pragma unroll
            for (int nt = 0; nt < 8; nt++) {
                uint32_t bh0, bh1, bh2, bh3, bl0, bl1, bl2, bl3;
                ldsm_x4(bh_base + swz_v(nt * 16 + b_row, 2 * kk + b_ch), bh0, bh1, bh2, bh3);
                ldsm_x4(bl_base + swz_v(nt * 16 + b_row, 2 * kk + b_ch), bl0, bl1, bl2, bl3);
                mma_bf16(C[2 * nt],     ah, bh0, bh1);
                mma_bf16(C[2 * nt + 1], ah, bh2, bh3);
                mma_bf16(C[2 * nt],     ah, bl0, bl1);
                mma_bf16(C[2 * nt + 1], ah, bl2, bl3);
                mma_bf16(C[2 * nt],     al, bh0, bh1);
                mma_bf16(C[2 * nt + 1], al, bh2, bh3);
            }
        }

        if (kc == 3) {
            if (wi == 0) {
                // Q: scale by log2e, split to fp16 hi/lo
                #pragma unroll
                for (int nt = 0; nt < 16; nt++) {
                    int d = nt * 8 + cq;
                    __half h0, l0, h1, l1;
                    split_h(C[nt][0] * LOG2E, h0, l0);
                    split_h(C[nt][1] * LOG2E, h1, l1);
                    size_t o0 = ((size_t)b * NT + n0 + q0 + r) * VC + d;
                    *(uint32_t*)(g_Qhi + o0) = pkh(h0, h1);
                    *(uint32_t*)(g_Qlo + o0) = pkh(l0, l1);
                    split_h(C[nt][2] * LOG2E, h0, l0);
                    split_h(C[nt][3] * LOG2E, h1, l1);
                    size_t o1 = o0 + (size_t)8 * VC;
                    *(uint32_t*)(g_Qhi + o1) = pkh(h0, h1);
                    *(uint32_t*)(g_Qlo + o1) = pkh(l0, l1);
                }
            } else if (wi == 1) {
                // K: single fp16
                #pragma unroll
                for (int nt = 0; nt < 16; nt++) {
                    int d = nt * 8 + cq;
                    size_t o0 = ((size_t)b * NT + n0 + q0 + r) * VC + d;
                    *(uint32_t*)(g_K + o0) = pkh(__float2half_rn(C[nt][0]),
                                                 __float2half_rn(C[nt][1]));
                    size_t o1 = o0 + (size_t)8 * VC;
                    *(uint32_t*)(g_K + o1) = pkh(__float2half_rn(C[nt][2]),
                                                 __float2half_rn(C[nt][3]));
                }
            } else {
                float* Vt = (float*)psm;   // 64 x 132 floats
                #pragma unroll
                for (int h = 0; h < 2; h++) {
                    __syncthreads();
                    #pragma unroll
                    for (int nt = h * 8; nt < h * 8 + 8; nt++) {
                        int dl = nt * 8 + cq - h * 64;
                        Vt[dl * 132 + q0 + r]           = C[nt][0];
                        Vt[(dl + 1) * 132 + q0 + r]     = C[nt][1];
                        Vt[dl * 132 + q0 + r + 8]       = C[nt][2];
                        Vt[(dl + 1) * 132 + q0 + r + 8] = C[nt][3];
                    }
                    __syncthreads();
                    #pragma unroll
                    for (int i = tid; i < 64 * 64; i += 256) {
                        int dd = i >> 6, n2 = i & 63;
                        __half2 hv = __floats2half2_rn(Vt[dd * 132 + n2 * 2],
                                                       Vt[dd * 132 + n2 * 2 + 1]);
                        *(__half2*)(g_V + ((size_t)b * VC + h * 64 + dd) * NT + n0 + n2 * 2) = hv;
                    }
                }
            }
        }
    }
}

// ---------------------------------------------------------------------------
// Flash attention: fp16 2-pass S (Qhi,Qlo x single-fp16 K) + fp16 single-pass
// PV, online-max (base-2), ex2 softmax interleaved with PV issue.
// smem (128KB): Qhi 0, Qlo 32K, K[2] 64K (16K bufs), V[2] 96K (16K bufs)
// ---------------------------------------------------------------------------
#define QHI_OFF 0
#define QLO_OFF 32768
#define K_OFF   65536
#define V_OFF   98304
#define KBUF 16384
#define S_TOTAL 131072

extern __shared__ char fa_sm[];

__device__ __forceinline__ void load_kv(uint32_t sbase, int b, int t, int buf, int tid)
{
    const int k0 = t * BN;
    // K single fp16: 64 rows x 16 chunks of 16B
    {
        uint32_t dst = sbase + K_OFF + buf * KBUF;
        #pragma unroll
        for (int i = tid; i < 64 * 16; i += 256) {
            int row = i >> 4, ch = i & 15;
            const char* g = (const char*)(g_K + ((size_t)b * NT + k0 + row) * VC) + ch * 16;
            CP_ASYNC16(dst + swz_q(row, ch), g);
        }
    }
    // V: 128 d-rows x 8 chunks (64 keys)
    {
        uint32_t dst = sbase + V_OFF + buf * KBUF;
        #pragma unroll
        for (int i = tid; i < 128 * 8; i += 256) {
            int row = i >> 3, ch = i & 7;
            const char* g = (const char*)(g_V + ((size_t)b * VC + row) * NT + k0) + ch * 16;
            CP_ASYNC16(dst + swz_v(row, ch), g);
        }
    }
}

__global__ __launch_bounds__(256, 1) void fa_kernel(float* __restrict__ out)
{
    const int tid  = threadIdx.x;
    const int w    = tid >> 5;
    const int lane = tid & 31;
    const int b    = blockIdx.y;
    const int n0   = blockIdx.x * BM;
    const int q0   = w * 16;

    char* sm = fa_sm;
    const uint32_t sbase = smem_u32(sm);

    // stage Q (fp16 hi/lo)
    #pragma unroll
    for (int comp = 0; comp < 2; comp++) {
        const __half* src = comp ? g_Qlo : g_Qhi;
        uint32_t dst = sbase + (comp ? QLO_OFF : QHI_OFF);
        #pragma unroll
        for (int i = tid; i < 128 * 16; i += 256) {
            int row = i >> 4, ch = i & 15;
            const char* g = (const char*)(src + ((size_t)b * NT + n0 + row) * VC) + ch * 16;
            CP_ASYNC16(dst + swz_q(row, ch), g);
        }
    }
    load_kv(sbase, b, 0, 0, tid);
    CP_COMMIT();

    float O[16][4];
    #pragma unroll
    for (int i = 0; i < 16; i++)
        #pragma unroll
        for (int j = 0; j < 4; j++) O[i][j] = 0.f;
    float rs0 = 0.f, rs1 = 0.f;
    float M0 = -1e30f, M1 = -1e30f;

    const int a_row = q0 + (lane & 15);
    const int a_ch  = (lane >> 4);
    const int b_row = (lane & 7) + ((lane >> 4) << 3);
    const int b_ch  = ((lane >> 3) & 1);

    #pragma unroll 1
    for (int t = 0; t < NTILES; t++) {
        const int buf = t & 1;
        if (t + 1 < NTILES) load_kv(sbase, b, t + 1, buf ^ 1, tid);
        CP_COMMIT();
        CP_WAIT1();
        __syncthreads();

        const uint32_t k_base = sbase + K_OFF + buf * KBUF;
        const uint32_t v_base = sbase + V_OFF + buf * KBUF;

        // ---- S = Q K^T: fp16 2-pass (Qhi*K + Qlo*K), base-2 logits ----
        float C[8][4];
        #pragma unroll
        for (int i = 0; i < 8; i++)
            #pragma unroll
            for (int j = 0; j < 4; j++) C[i][j] = 0.f;

        #pragma unroll
        for (int kc = 0; kc < 8; kc++) {
            uint32_t aqh[4], aql[4];
            ldsm_x4(sbase + QHI_OFF + swz_q(a_row, 2 * kc + a_ch),
                    aqh[0], aqh[1], aqh[2], aqh[3]);
            ldsm_x4(sbase + QLO_OFF + swz_q(a_row, 2 * kc + a_ch),
                    aql[0], aql[1], aql[2], aql[3]);
            #pragma unroll
            for (int ntp = 0; ntp < 4; ntp++) {
                uint32_t k0r, k1r, k2r, k3r;
                ldsm_x4(k_base + swz_q(ntp * 16 + b_row, 2 * kc + b_ch),
                        k0r, k1r, k2r, k3r);
                mma_f16(C[2 * ntp],     aqh, k0r, k1r);
                mma_f16(C[2 * ntp + 1], aqh, k2r, k3r);
                mma_f16(C[2 * ntp],     aql, k0r, k1r);
                mma_f16(C[2 * ntp + 1], aql, k2r, k3r);
            }
        }

        // ---- row max + rescale ----
        float tm0 = -1e30f, tm1 = -1e30f;
        #pragma unroll
        for (int nt = 0; nt < 8; nt++) {
            tm0 = fmaxf(tm0, fmaxf(C[nt][0], C[nt][1]));
            tm1 = fmaxf(tm1, fmaxf(C[nt][2], C[nt][3]));
        }
        tm0 = fmaxf(tm0, __shfl_xor_sync(0xffffffffu, tm0, 1));
        tm0 = fmaxf(tm0, __shfl_xor_sync(0xffffffffu, tm0, 2));
        tm1 = fmaxf(tm1, __shfl_xor_sync(0xffffffffu, tm1, 1));
        tm1 = fmaxf(tm1, __shfl_xor_sync(0xffffffffu, tm1, 2));
        const float M0n = fmaxf(M0, tm0);
        const float M1n = fmaxf(M1, tm1);
        const float s0 = ex2(M0 - M0n);
        const float s1 = ex2(M1 - M1n);
        M0 = M0n; M1 = M1n;
        rs0 *= s0; rs1 *= s1;

        if (!__all_sync(0xffffffffu, (s0 == 1.0f) & (s1 == 1.0f))) {
            #pragma unroll
            for (int nt = 0; nt < 16; nt++) {
                O[nt][0] *= s0; O[nt][1] *= s0;
                O[nt][2] *= s1; O[nt][3] *= s1;
            }
        }

        // ---- interleaved: per kc group, softmax (exp2/pack) then PV mma ----
        #pragma unroll
        for (int kc = 0; kc < 4; kc++) {
            uint32_t aph[4];
            {
                const int nt = 2 * kc;
                float p0 = ex2(C[nt][0] - M0), p1 = ex2(C[nt][1] - M0);
                float p2 = ex2(C[nt][2] - M1), p3 = ex2(C[nt][3] - M1);
                rs0 += p0 + p1; rs1 += p2 + p3;
                aph[0] = pkh(__float2half_rn(p0), __float2half_rn(p1));
                aph[1] = pkh(__float2half_rn(p2), __float2half_rn(p3));
                p0 = ex2(C[nt + 1][0] - M0); p1 = ex2(C[nt + 1][1] - M0);
                p2 = ex2(C[nt + 1][2] - M1); p3 = ex2(C[nt + 1][3] - M1);
                rs0 += p0 + p1; rs1 += p2 + p3;
                aph[2] = pkh(__float2half_rn(p0), __float2half_rn(p1));
                aph[3] = pkh(__float2half_rn(p2), __float2half_rn(p3));
            }
            #pragma unroll
            for (int ntp = 0; ntp < 8; ntp++) {
                uint32_t v0, v1, v2, v3;
                ldsm_x4(v_base + swz_v(ntp * 16 + b_row, 2 * kc + b_ch),
                        v0, v1, v2, v3);
                mma_f16(O[2 * ntp],     aph, v0, v1);
                mma_f16(O[2 * ntp + 1], aph, v2, v3);
            }
        }
        __syncthreads();   // all warps done with buf before it is refilled
    }

    // ---- finalize ----
    rs0 += __shfl_xor_sync(0xffffffffu, rs0, 1);
    rs0 += __shfl_xor_sync(0xffffffffu, rs0, 2);
    rs1 += __shfl_xor_sync(0xffffffffu, rs1, 1);
    rs1 += __shfl_xor_sync(0xffffffffu, rs1, 2);
    const float inv0 = 1.0f / rs0;
    const float inv1 = 1.0f / rs1;

    __syncthreads();
    float* Ot = (float*)sm;   // 128x132 floats (67584B) — smem fully free now
    const int r  = lane >> 2;
    const int cc = (lane & 3) * 2;
    #pragma unroll
    for (int nt = 0; nt < 16; nt++) {
        int d = nt * 8 + cc;
        Ot[d * 132 + q0 + r]           = O[nt][0] * inv0;
        Ot[(d + 1) * 132 + q0 + r]     = O[nt][1] * inv0;
        Ot[d * 132 + q0 + r + 8]       = O[nt][2] * inv1;
        Ot[(d + 1) * 132 + q0 + r + 8] = O[nt][3] * inv1;
    }
    __syncthreads();

    float* outb = out + (size_t)b * VC * NT;
    #pragma unroll
    for (int i = tid; i < VC * BM; i += 256) {
        int d = i >> 7, q = i & 127;
        outb[(size_t)d * NT + n0 + q] = Ot[d * 132 + q];
    }
}

// ---------------------------------------------------------------------------
extern "C" void kernel_launch(void* const* d_in, const int* in_sizes, int n_in,
                              void* d_out, int out_size)
{
    const float* x  = (const float*)d_in[0];
    const float* Wq = (const float*)d_in[1];
    const float* Wk = (const float*)d_in[2];
    const float* Wv = (const float*)d_in[3];
    float* out = (float*)d_out;

    wsplit_kernel<<<3 * VC * Cc / 4 / 256, 256>>>(Wq, Wk, Wv);

    dim3 g0(NT / 64, Cc / 64, Bb);
    xsplit_kernel<<<g0, 256>>>(x);

    cudaFuncSetAttribute(proj_fused_kernel, cudaFuncAttributeMaxDynamicSharedMemorySize, PF_SMEM);
    dim3 g1(NT / 128, Bb);
    proj_fused_kernel<<<g1, 256, PF_SMEM>>>();

    cudaFuncSetAttribute(fa_kernel, cudaFuncAttributeMaxDynamicSharedMemorySize, S_TOTAL);
    dim3 g2(NT / BM, Bb);
    fa_kernel<<<g2, 256, S_TOTAL>>>(out);
}

// round 15
// speedup vs baseline: 1.4657x; 1.1953x over previous
#include <cuda_runtime.h>
#include <cuda_bf16.h>
#include <cuda_fp16.h>
#include <cstdint>

// ---------------------------------------------------------------------------
// Problem constants
// ---------------------------------------------------------------------------
#define Bb 4
#define Cc 256
#define VC 128
#define NT 4096          // H*W
#define BM 128           // queries per CTA
#define BN 64            // keys per tile
#define NTILES (NT / BN) // 64
#define LOG2E 1.4426950408889634f

// Scratch
__device__ __nv_bfloat16 g_xhi[Bb * NT * Cc];   // x split, [b][n][c]
__device__ __nv_bfloat16 g_xlo[Bb * NT * Cc];
__device__ __nv_bfloat16 g_Whi[3 * VC * Cc];    // W split, [wi][d][c]
__device__ __nv_bfloat16 g_Wlo[3 * VC * Cc];
__device__ __half        g_Q  [Bb * NT * VC];   // Q*log2e fp16, [b][n][d]
__device__ __half        g_K  [Bb * NT * VC];   // K fp16, [b][n][d]
__device__ __half        g_V  [Bb * VC * NT];   // V fp16, [b][d][n]

// ---------------------------------------------------------------------------
// helpers
// ---------------------------------------------------------------------------
__device__ __forceinline__ uint32_t smem_u32(const void* p) {
    uint32_t a;
    asm("{ .reg .u64 t; cvta.to.shared.u64 t, %1; cvt.u32.u64 %0, t; }"
        : "=r"(a) : "l"(p));
    return a;
}
__device__ __forceinline__ float ex2(float x) {
    float y;
    asm("ex2.approx.ftz.f32 %0, %1;" : "=f"(y) : "f"(x));
    return y;
}

#define CP_ASYNC16(dst, src) \
    asm volatile("cp.async.cg.shared.global [%0], [%1], 16;" \
                 :: "r"(dst), "l"(src) : "memory")
#define CP_COMMIT() asm volatile("cp.async.commit_group;" ::: "memory")
#define CP_WAIT1()  asm volatile("cp.async.wait_group 1;" ::: "memory")
#define CP_WAIT0()  asm volatile("cp.async.wait_group 0;" ::: "memory")

__device__ __forceinline__ void ldsm_x4(uint32_t addr, uint32_t& r0, uint32_t& r1,
                                        uint32_t& r2, uint32_t& r3) {
    asm volatile("ldmatrix.sync.aligned.m8n8.x4.shared.b16 {%0,%1,%2,%3}, [%4];"
                 : "=r"(r0), "=r"(r1), "=r"(r2), "=r"(r3) : "r"(addr));
}

__device__ __forceinline__ void mma_bf16(float* c, const uint32_t a[4],
                                         uint32_t b0, uint32_t b1) {
    asm volatile(
        "mma.sync.aligned.m16n8k16.row.col.f32.bf16.bf16.f32 "
        "{%0,%1,%2,%3}, {%4,%5,%6,%7}, {%8,%9}, {%0,%1,%2,%3};"
        : "+f"(c[0]), "+f"(c[1]), "+f"(c[2]), "+f"(c[3])
        : "r"(a[0]), "r"(a[1]), "r"(a[2]), "r"(a[3]), "r"(b0), "r"(b1));
}
__device__ __forceinline__ void mma_f16(float* c, const uint32_t a[4],
                                        uint32_t b0, uint32_t b1) {
    asm volatile(
        "mma.sync.aligned.m16n8k16.row.col.f32.f16.f16.f32 "
        "{%0,%1,%2,%3}, {%4,%5,%6,%7}, {%8,%9}, {%0,%1,%2,%3};"
        : "+f"(c[0]), "+f"(c[1]), "+f"(c[2]), "+f"(c[3])
        : "r"(a[0]), "r"(a[1]), "r"(a[2]), "r"(a[3]), "r"(b0), "r"(b1));
}

__device__ __forceinline__ void split_bf(float v, __nv_bfloat16& h, __nv_bfloat16& l) {
    h = __float2bfloat16_rn(v);
    l = __float2bfloat16_rn(v - __bfloat162float(h));
}
__device__ __forceinline__ uint32_t pk(__nv_bfloat16 a, __nv_bfloat16 b) {
    __nv_bfloat162 t = __halves2bfloat162(a, b);
    uint32_t u;
    *reinterpret_cast<__nv_bfloat162*>(&u) = t;
    return u;
}
__device__ __forceinline__ uint32_t pkh(__half a, __half b) {
    __half2 t = __halves2half2(a, b);
    uint32_t u;
    *reinterpret_cast<__half2*>(&u) = t;
    return u;
}

// swizzled byte offsets: 256B rows (16 chunks of 16B), 128B rows (8 chunks)
__device__ __forceinline__ uint32_t swz_q(int row, int ch) {
    return (uint32_t)(row * 256 + ((ch ^ (row & 7)) << 4));
}
__device__ __forceinline__ uint32_t swz_v(int row, int ch) {
    return (uint32_t)(row * 128 + ((ch ^ (row & 7)) << 4));
}

// ---------------------------------------------------------------------------
// W split: Wq/Wk/Wv [d][c] fp32 -> g_Whi/g_Wlo bf16 [wi][d][c]
// ---------------------------------------------------------------------------
__global__ __launch_bounds__(256) void wsplit_kernel(
    const float* __restrict__ Wq,
    const float* __restrict__ Wk,
    const float* __restrict__ Wv)
{
    const int idx = blockIdx.x * 256 + threadIdx.x;
    const int f0  = idx * 4;
    const int wi  = f0 / (VC * Cc);
    const int off = f0 - wi * (VC * Cc);
    const float* W = (wi == 0) ? Wq : (wi == 1) ? Wk : Wv;
    float4 v = *(const float4*)(W + off);
    __nv_bfloat16 h0, l0, h1, l1, h2, l2, h3, l3;
    split_bf(v.x, h0, l0); split_bf(v.y, h1, l1);
    split_bf(v.z, h2, l2); split_bf(v.w, h3, l3);
    size_t o = (size_t)wi * VC * Cc + off;
    *(uint2*)(g_Whi + o) = make_uint2(pk(h0, h1), pk(h2, h3));
    *(uint2*)(g_Wlo + o) = make_uint2(pk(l0, l1), pk(l2, l3));
}

// ---------------------------------------------------------------------------
// x split/transpose: x [b][c][n] fp32 -> g_xhi/g_xlo [b][n][c] bf16.
// ---------------------------------------------------------------------------
__global__ __launch_bounds__(256) void xsplit_kernel(const float* __restrict__ x)
{
    __shared__ float T[64][65];
    const int b  = blockIdx.z;
    const int c0 = blockIdx.y * 64;
    const int n0 = blockIdx.x * 64;
    const int tid = threadIdx.x;

    #pragma unroll
    for (int i = tid; i < 64 * 16; i += 256) {
        int c = i >> 4, n4 = i & 15;
        float4 v = *(const float4*)(x + ((size_t)b * Cc + c0 + c) * NT + n0 + n4 * 4);
        T[c][n4 * 4 + 0] = v.x; T[c][n4 * 4 + 1] = v.y;
        T[c][n4 * 4 + 2] = v.z; T[c][n4 * 4 + 3] = v.w;
    }
    __syncthreads();
    #pragma unroll
    for (int i = tid; i < 64 * 32; i += 256) {
        int n = i >> 5, c2 = i & 31;
        float f0 = T[c2 * 2][n], f1 = T[c2 * 2 + 1][n];
        __nv_bfloat16 h0, l0, h1, l1;
        split_bf(f0, h0, l0);
        split_bf(f1, h1, l1);
        size_t off = ((size_t)b * NT + n0 + n) * Cc + c0 + c2 * 2;
        *(uint32_t*)(g_xhi + off) = pk(h0, h1);
        *(uint32_t*)(g_xlo + off) = pk(l0, l1);
    }
}

// ---------------------------------------------------------------------------
// Fused QKV projection (split-bf16, 3-pass). A staged once, B double-buffered.
// Epilogue: Q -> fp16 (scaled log2e), K -> fp16, V -> fp16 [b][d][n].
// grid (NT/128, Bb), 256 threads, smem 192KB.
// ---------------------------------------------------------------------------
#define FA_OFF(kc, comp) (((kc) * 2 + (comp)) * 16384)
#define FB_OFF 131072
#define FB_BUF 32768
#define PF_SMEM 196608

extern __shared__ char proj_sm[];

__device__ __forceinline__ void proj_load_B(uint32_t sb, int wi, int kc, int buf, int tid)
{
    #pragma unroll
    for (int i = tid; i < 2048; i += 256) {
        int comp = i >> 10, row = (i >> 3) & 127, ch = i & 7;
        const __nv_bfloat16* src = comp ? g_Wlo : g_Whi;
        const char* g = (const char*)(src + (size_t)wi * VC * Cc + (size_t)row * Cc + kc * 64)
                        + ch * 16;
        CP_ASYNC16(sb + FB_OFF + buf * FB_BUF + comp * 16384 + swz_v(row, ch), g);
    }
}

__global__ __launch_bounds__(256, 1) void proj_fused_kernel()
{
    const int b  = blockIdx.y;
    const int n0 = blockIdx.x * 128;

    const int tid  = threadIdx.x;
    const int w    = tid >> 5;
    const int lane = tid & 31;
    const int q0   = w * 16;

    char* psm = proj_sm;
    const uint32_t sb = smem_u32(psm);

    const int a_row = q0 + (lane & 15);
    const int a_c16 = lane >> 4;
    const int b_row = (lane & 7) + ((lane >> 4) << 3);
    const int b_ch  = (lane >> 3) & 1;

    #pragma unroll
    for (int i = tid; i < 8192; i += 256) {
        int comp = i >> 12;
        int rem  = i & 4095;
        int kc   = rem >> 10;
        int row  = (rem >> 3) & 127;
        int ch   = rem & 7;
        const __nv_bfloat16* src = comp ? g_xlo : g_xhi;
        const char* g = (const char*)(src + ((size_t)b * NT + n0 + row) * Cc + kc * 64)
                        + ch * 16;
        CP_ASYNC16(sb + FA_OFF(kc, comp) + swz_v(row, ch), g);
    }
    proj_load_B(sb, 0, 0, 0, tid);
    CP_COMMIT();

    float C[16][4];
    const int r  = lane >> 2;
    const int cq = (lane & 3) * 2;

    #pragma unroll 1
    for (int it = 0; it < 12; it++) {
        const int wi  = it >> 2;
        const int kc  = it & 3;
        const int buf = it & 1;

        if (kc == 0) {
            #pragma unroll
            for (int i = 0; i < 16; i++)
                #pragma unroll
                for (int j = 0; j < 4; j++) C[i][j] = 0.f;
        }

        __syncthreads();
        if (it + 1 < 12) {
            proj_load_B(sb, (it + 1) >> 2, (it + 1) & 3, buf ^ 1, tid);
            CP_COMMIT();
            CP_WAIT1();
        } else {
            CP_WAIT0();
        }
        __syncthreads();

        const uint32_t bh_base = sb + FB_OFF + buf * FB_BUF;
        const uint32_t bl_base = bh_base + 16384;
        const uint32_t ah_base = sb + FA_OFF(kc, 0);
        const uint32_t al_base = sb + FA_OFF(kc, 1);

        #pragma unroll
        for (int kk = 0; kk < 4; kk++) {
            uint32_t ah[4], al[4];
            ldsm_x4(ah_base + swz_v(a_row, 2 * kk + a_c16), ah[0], ah[1], ah[2], ah[3]);
            ldsm_x4(al_base + swz_v(a_row, 2 * kk + a_c16), al[0], al[1], al[2], al[3]);
            #pragma unroll
            for (int nt = 0; nt < 8; nt++) {
                uint32_t bh0, bh1, bh2, bh3, bl0, bl1, bl2, bl3;
                ldsm_x4(bh_base + swz_v(nt * 16 + b_row, 2 * kk + b_ch), bh0, bh1, bh2, bh3);
                ldsm_x4(bl_base + swz_v(nt * 16 + b_row, 2 * kk + b_ch), bl0, bl1, bl2, bl3);
                mma_bf16(C[2 * nt],     ah, bh0, bh1);
                mma_bf16(C[2 * nt + 1], ah, bh2, bh3);
                mma_bf16(C[2 * nt],     ah, bl0, bl1);
                mma_bf16(C[2 * nt + 1], ah, bl2, bl3);
                mma_bf16(C[2 * nt],     al, bh0, bh1);
                mma_bf16(C[2 * nt + 1], al, bh2, bh3);
            }
        }

        if (kc == 3) {
            if (wi < 2) {
                // Q (scaled by log2e) or K -> single fp16 [b][n][d]
                __half* dst = (wi == 0) ? g_Q : g_K;
                const float sc = (wi == 0) ? LOG2E : 1.0f;
                #pragma unroll
                for (int nt = 0; nt < 16; nt++) {
                    int d = nt * 8 + cq;
                    size_t o0 = ((size_t)b * NT + n0 + q0 + r) * VC + d;
                    *(uint32_t*)(dst + o0) = pkh(__float2half_rn(C[nt][0] * sc),
                                                 __float2half_rn(C[nt][1] * sc));
                    size_t o1 = o0 + (size_t)8 * VC;
                    *(uint32_t*)(dst + o1) = pkh(__float2half_rn(C[nt][2] * sc),
                                                 __float2half_rn(C[nt][3] * sc));
                }
            } else {
                float* Vt = (float*)psm;   // 64 x 132 floats
                #pragma unroll
                for (int h = 0; h < 2; h++) {
                    __syncthreads();
                    #pragma unroll
                    for (int nt = h * 8; nt < h * 8 + 8; nt++) {
                        int dl = nt * 8 + cq - h * 64;
                        Vt[dl * 132 + q0 + r]           = C[nt][0];
                        Vt[(dl + 1) * 132 + q0 + r]     = C[nt][1];
                        Vt[dl * 132 + q0 + r + 8]       = C[nt][2];
                        Vt[(dl + 1) * 132 + q0 + r + 8] = C[nt][3];
                    }
                    __syncthreads();
                    #pragma unroll
                    for (int i = tid; i < 64 * 64; i += 256) {
                        int dd = i >> 6, n2 = i & 63;
                        __half2 hv = __floats2half2_rn(Vt[dd * 132 + n2 * 2],
                                                       Vt[dd * 132 + n2 * 2 + 1]);
                        *(__half2*)(g_V + ((size_t)b * VC + h * 64 + dd) * NT + n0 + n2 * 2) = hv;
                    }
                }
            }
        }
    }
}

// ---------------------------------------------------------------------------
// Flash attention: fp16 single-pass S (Q x K) + fp16 single-pass PV,
// online-max (base-2), ex2 softmax interleaved with PV issue.
// smem (96KB): Q 0 (32K), K[2] 32K (16K bufs), V[2] 64K (16K bufs)
// ---------------------------------------------------------------------------
#define Q_OFF   0
#define K_OFF   32768
#define V_OFF   65536
#define KBUF 16384
#define S_TOTAL 98304

extern __shared__ char fa_sm[];

__device__ __forceinline__ void load_kv(uint32_t sbase, int b, int t, int buf, int tid)
{
    const int k0 = t * BN;
    // K fp16: 64 rows x 16 chunks of 16B
    {
        uint32_t dst = sbase + K_OFF + buf * KBUF;
        #pragma unroll
        for (int i = tid; i < 64 * 16; i += 256) {
            int row = i >> 4, ch = i & 15;
            const char* g = (const char*)(g_K + ((size_t)b * NT + k0 + row) * VC) + ch * 16;
            CP_ASYNC16(dst + swz_q(row, ch), g);
        }
    }
    // V: 128 d-rows x 8 chunks (64 keys)
    {
        uint32_t dst = sbase + V_OFF + buf * KBUF;
        #pragma unroll
        for (int i = tid; i < 128 * 8; i += 256) {
            int row = i >> 3, ch = i & 7;
            const char* g = (const char*)(g_V + ((size_t)b * VC + row) * NT + k0) + ch * 16;
            CP_ASYNC16(dst + swz_v(row, ch), g);
        }
    }
}

__global__ __launch_bounds__(256, 1) void fa_kernel(float* __restrict__ out)
{
    const int tid  = threadIdx.x;
    const int w    = tid >> 5;
    const int lane = tid & 31;
    const int b    = blockIdx.y;
    const int n0   = blockIdx.x * BM;
    const int q0   = w * 16;

    char* sm = fa_sm;
    const uint32_t sbase = smem_u32(sm);

    // stage Q (fp16)
    #pragma unroll
    for (int i = tid; i < 128 * 16; i += 256) {
        int row = i >> 4, ch = i & 15;
        const char* g = (const char*)(g_Q + ((size_t)b * NT + n0 + row) * VC) + ch * 16;
        CP_ASYNC16(sbase + Q_OFF + swz_q(row, ch), g);
    }
    load_kv(sbase, b, 0, 0, tid);
    CP_COMMIT();

    float O[16][4];
    #pragma unroll
    for (int i = 0; i < 16; i++)
        #pragma unroll
        for (int j = 0; j < 4; j++) O[i][j] = 0.f;
    float rs0 = 0.f, rs1 = 0.f;
    float M0 = -1e30f, M1 = -1e30f;

    const int a_row = q0 + (lane & 15);
    const int a_ch  = (lane >> 4);
    const int b_row = (lane & 7) + ((lane >> 4) << 3);
    const int b_ch  = ((lane >> 3) & 1);

    #pragma unroll 1
    for (int t = 0; t < NTILES; t++) {
        const int buf = t & 1;
        if (t + 1 < NTILES) load_kv(sbase, b, t + 1, buf ^ 1, tid);
        CP_COMMIT();
        CP_WAIT1();
        __syncthreads();

        const uint32_t k_base = sbase + K_OFF + buf * KBUF;
        const uint32_t v_base = sbase + V_OFF + buf * KBUF;

        // ---- S = Q K^T: fp16 single pass, base-2 logits (Q pre-scaled) ----
        float C[8][4];
        #pragma unroll
        for (int i = 0; i < 8; i++)
            #pragma unroll
            for (int j = 0; j < 4; j++) C[i][j] = 0.f;

        #pragma unroll
        for (int kc = 0; kc < 8; kc++) {
            uint32_t aq[4];
            ldsm_x4(sbase + Q_OFF + swz_q(a_row, 2 * kc + a_ch),
                    aq[0], aq[1], aq[2], aq[3]);
            #pragma unroll
            for (int ntp = 0; ntp < 4; ntp++) {
                uint32_t k0r, k1r, k2r, k3r;
                ldsm_x4(k_base + swz_q(ntp * 16 + b_row, 2 * kc + b_ch),
                        k0r, k1r, k2r, k3r);
                mma_f16(C[2 * ntp],     aq, k0r, k1r);
                mma_f16(C[2 * ntp + 1], aq, k2r, k3r);
            }
        }

        // ---- row max + rescale ----
        float tm0 = -1e30f, tm1 = -1e30f;
        #pragma unroll
        for (int nt = 0; nt < 8; nt++) {
            tm0 = fmaxf(tm0, fmaxf(C[nt][0], C[nt][1]));
            tm1 = fmaxf(tm1, fmaxf(C[nt][2], C[nt][3]));
        }
        tm0 = fmaxf(tm0, __shfl_xor_sync(0xffffffffu, tm0, 1));
        tm0 = fmaxf(tm0, __shfl_xor_sync(0xffffffffu, tm0, 2));
        tm1 = fmaxf(tm1, __shfl_xor_sync(0xffffffffu, tm1, 1));
        tm1 = fmaxf(tm1, __shfl_xor_sync(0xffffffffu, tm1, 2));
        const float M0n = fmaxf(M0, tm0);
        const float M1n = fmaxf(M1, tm1);
        const float s0 = ex2(M0 - M0n);
        const float s1 = ex2(M1 - M1n);
        M0 = M0n; M1 = M1n;
        rs0 *= s0; rs1 *= s1;

        if (!__all_sync(0xffffffffu, (s0 == 1.0f) & (s1 == 1.0f))) {
            #pragma unroll
            for (int nt = 0; nt < 16; nt++) {
                O[nt][0] *= s0; O[nt][1] *= s0;
                O[nt][2] *= s1; O[nt][3] *= s1;
            }
        }

        // ---- interleaved: per kc group, softmax (exp2/pack) then PV mma ----
        #pragma unroll
        for (int kc = 0; kc < 4; kc++) {
            uint32_t aph[4];
            {
                const int nt = 2 * kc;
                float p0 = ex2(C[nt][0] - M0), p1 = ex2(C[nt][1] - M0);
                float p2 = ex2(C[nt][2] - M1), p3 = ex2(C[nt][3] - M1);
                rs0 += p0 + p1; rs1 += p2 + p3;
                aph[0] = pkh(__float2half_rn(p0), __float2half_rn(p1));
                aph[1] = pkh(__float2half_rn(p2), __float2half_rn(p3));
                p0 = ex2(C[nt + 1][0] - M0); p1 = ex2(C[nt + 1][1] - M0);
                p2 = ex2(C[nt + 1][2] - M1); p3 = ex2(C[nt + 1][3] - M1);
                rs0 += p0 + p1; rs1 += p2 + p3;
                aph[2] = pkh(__float2half_rn(p0), __float2half_rn(p1));
                aph[3] = pkh(__float2half_rn(p2), __float2half_rn(p3));
            }
            #pragma unroll
            for (int ntp = 0; ntp < 8; ntp++) {
                uint32_t v0, v1, v2, v3;
                ldsm_x4(v_base + swz_v(ntp * 16 + b_row, 2 * kc + b_ch),
                        v0, v1, v2, v3);
                mma_f16(O[2 * ntp],     aph, v0, v1);
                mma_f16(O[2 * ntp + 1], aph, v2, v3);
            }
        }
        __syncthreads();   // all warps done with buf before it is refilled
    }

    // ---- finalize ----
    rs0 += __shfl_xor_sync(0xffffffffu, rs0, 1);
    rs0 += __shfl_xor_sync(0xffffffffu, rs0, 2);
    rs1 += __shfl_xor_sync(0xffffffffu, rs1, 1);
    rs1 += __shfl_xor_sync(0xffffffffu, rs1, 2);
    const float inv0 = 1.0f / rs0;
    const float inv1 = 1.0f / rs1;

    __syncthreads();
    float* Ot = (float*)sm;   // 128x132 floats (67584B) fits in 96KB smem
    const int r  = lane >> 2;
    const int cc = (lane & 3) * 2;
    #pragma unroll
    for (int nt = 0; nt < 16; nt++) {
        int d = nt * 8 + cc;
        Ot[d * 132 + q0 + r]           = O[nt][0] * inv0;
        Ot[(d + 1) * 132 + q0 + r]     = O[nt][1] * inv0;
        Ot[d * 132 + q0 + r + 8]       = O[nt][2] * inv1;
        Ot[(d + 1) * 132 + q0 + r + 8] = O[nt][3] * inv1;
    }
    __syncthreads();

    float* outb = out + (size_t)b * VC * NT;
    #pragma unroll
    for (int i = tid; i < VC * BM; i += 256) {
        int d = i >> 7, q = i & 127;
        outb[(size_t)d * NT + n0 + q] = Ot[d * 132 + q];
    }
}

// ---------------------------------------------------------------------------
extern "C" void kernel_launch(void* const* d_in, const int* in_sizes, int n_in,
                              void* d_out, int out_size)
{
    const float* x  = (const float*)d_in[0];
    const float* Wq = (const float*)d_in[1];
    const float* Wk = (const float*)d_in[2];
    const float* Wv = (const float*)d_in[3];
    float* out = (float*)d_out;

    wsplit_kernel<<<3 * VC * Cc / 4 / 256, 256>>>(Wq, Wk, Wv);

    dim3 g0(NT / 64, Cc / 64, Bb);
    xsplit_kernel<<<g0, 256>>>(x);

    cudaFuncSetAttribute(proj_fused_kernel, cudaFuncAttributeMaxDynamicSharedMemorySize, PF_SMEM);
    dim3 g1(NT / 128, Bb);
    proj_fused_kernel<<<g1, 256, PF_SMEM>>>();

    cudaFuncSetAttribute(fa_kernel, cudaFuncAttributeMaxDynamicSharedMemorySize, S_TOTAL);
    dim3 g2(NT / BM, Bb);
    fa_kernel<<<g2, 256, S_TOTAL>>>(out);
}